// round 15
// baseline (speedup 1.0000x reference)
#include <cuda_runtime.h>
#include <cuda_bf16.h>

#define B_  8
#define H_  8
#define N_  512
#define K_  16
#define BN  (B_*N_)          // 4096
#define NN  (N_*N_)          // 262144

__device__ float g_A[BN * 256];     // per-(b,n) algebra element A, row-major 16x16
__device__ float g_V[BN * K_];      // v = exp(-A) mu

// ---------------------------------------------------------------------------
// Warp-collective: y = exp(A) x for a 16x16 A (M-term Taylor, Horner).
// Lane l owns row r = l&15 of A. x_own = component r of x (lanes 16-31 mirror).
// ---------------------------------------------------------------------------
template<int M>
__device__ __forceinline__ float exp_apply(const float Ar[16], float x_own) {
    float x[16], y[16];
    #pragma unroll
    for (int c = 0; c < 16; ++c) {
        x[c] = __shfl_sync(0xffffffffu, x_own, c);
        y[c] = x[c];
    }
    float y_own = x_own;
    #pragma unroll
    for (int k = M; k >= 1; --k) {
        float z0 = 0.0f, z1 = 0.0f;
        #pragma unroll
        for (int c = 0; c < 16; c += 2) {
            z0 += Ar[c]     * y[c];
            z1 += Ar[c + 1] * y[c + 1];
        }
        float zk = (z0 + z1) * (1.0f / (float)k);
        y_own = x_own + zk;
        #pragma unroll
        for (int c = 0; c < 16; ++c)
            y[c] = x[c] + __shfl_sync(0xffffffffu, zk, c);
    }
    return y_own;
}

// ---------------------------------------------------------------------------
// Kernel 0: per (b,n): A = sum_g phi_g G_g (store), v = exp(-A) mu (store).
// ---------------------------------------------------------------------------
__global__ __launch_bounds__(256)
void prep_kernel(const float* __restrict__ mu,
                 const float* __restrict__ phi,
                 const float* __restrict__ gen) {
    int w = threadIdx.x >> 5, lane = threadIdx.x & 31, r = lane & 15;
    int bn = blockIdx.x * 8 + w;

    float p0 = phi[bn * 3 + 0], p1 = phi[bn * 3 + 1], p2 = phi[bn * 3 + 2];

    float Ar[16];
    const float4* g4 = (const float4*)gen;
    #pragma unroll
    for (int q = 0; q < 4; ++q) {
        float4 a = g4[(0 * 256 + r * 16) / 4 + q];
        float4 b = g4[(1 * 256 + r * 16) / 4 + q];
        float4 c = g4[(2 * 256 + r * 16) / 4 + q];
        Ar[4 * q + 0] = p0 * a.x + p1 * b.x + p2 * c.x;
        Ar[4 * q + 1] = p0 * a.y + p1 * b.y + p2 * c.y;
        Ar[4 * q + 2] = p0 * a.z + p1 * b.z + p2 * c.z;
        Ar[4 * q + 3] = p0 * a.w + p1 * b.w + p2 * c.w;
    }
    if (lane < 16) {
        float4* A4 = (float4*)(g_A + (size_t)bn * 256 + r * 16);
        #pragma unroll
        for (int q = 0; q < 4; ++q)
            A4[q] = make_float4(Ar[4*q], Ar[4*q+1], Ar[4*q+2], Ar[4*q+3]);
    }

    float nAr[16];
    #pragma unroll
    for (int c = 0; c < 16; ++c) nAr[c] = -Ar[c];

    float x_own = mu[bn * 16 + r];
    float v = exp_apply<16>(nAr, x_own);
    if (lane < 16) g_V[bn * 16 + lane] = v;
}

// ---------------------------------------------------------------------------
// Kernel 1: fused stream+compute (R13 structure), 3 blocks/SM.
// Phase A streams this block's beta slice (8 rows x 8 heads, 64 KB) with the
// head-sum done in two 4-head batches (only 4-5 float4 live -> fits 85 regs).
// Phase B is the proven conflict-free loop + reduce-scatter epilogue.
// With 24 warps/SM the DRAM duty cycle rises; spill traffic (if any) hides
// under the stream.
// ---------------------------------------------------------------------------
__global__ __launch_bounds__(256, 3)
void vffn_main_kernel(const float* __restrict__ beta,
                      const float* __restrict__ mu,
                      const float* __restrict__ mu_prior,
                      const float* __restrict__ lr_ptr,
                      float* __restrict__ out) {
    __shared__ float Vs[N_ * 20];      // 40 KB, stride-20 conflict-free
    __shared__ float qs[N_];           //  2 KB
    __shared__ float cbs[8 * N_];      // 16 KB: 8 rows x 512 head-avg values

    int t = threadIdx.x, lane = t & 31, w = t >> 5, r = lane & 15;
    int b = blockIdx.x >> 6;                 // 64 blocks per batch
    int i0 = (blockIdx.x & 63) << 3;
    int i = i0 + w;                          // this warp's row
    int bn = b * N_ + i;
    float lr = *lr_ptr;

    // ---- Phase A: stream beta rows [i0,i0+8) over 8 heads, head-summed.
    // Two 4-head batches per position: 4 independent LDG.128 in flight each,
    // low register pressure. __ldcs: read-once stream, evict-first.
    {
        const float4* bb4 = (const float4*)(beta + (size_t)b * H_ * NN + (size_t)i0 * N_);
        const int HS = NN / 4;               // float4 stride between heads
        float4* cb4 = (float4*)cbs;
        #pragma unroll
        for (int s0 = 0; s0 < 1024; s0 += 256) {
            int s = s0 + t;
            float4 h0 = __ldcs(bb4 + s + 0*HS);
            float4 h1 = __ldcs(bb4 + s + 1*HS);
            float4 h2 = __ldcs(bb4 + s + 2*HS);
            float4 h3 = __ldcs(bb4 + s + 3*HS);
            float4 p;
            p.x = (h0.x + h1.x) + (h2.x + h3.x);
            p.y = (h0.y + h1.y) + (h2.y + h3.y);
            p.z = (h0.z + h1.z) + (h2.z + h3.z);
            p.w = (h0.w + h1.w) + (h2.w + h3.w);
            float4 h4 = __ldcs(bb4 + s + 4*HS);
            float4 h5 = __ldcs(bb4 + s + 5*HS);
            float4 h6 = __ldcs(bb4 + s + 6*HS);
            float4 h7 = __ldcs(bb4 + s + 7*HS);
            float4 o;
            o.x = (p.x + ((h4.x + h5.x) + (h6.x + h7.x))) * 0.125f;
            o.y = (p.y + ((h4.y + h5.y) + (h6.y + h7.y))) * 0.125f;
            o.z = (p.z + ((h4.z + h5.z) + (h6.z + h7.z))) * 0.125f;
            o.w = (p.w + ((h4.w + h5.w) + (h6.w + h7.w))) * 0.125f;
            cb4[s] = o;
        }
    }
    // Stage V[b] into padded smem (stride 20 floats; float4-aligned)
    const float4* V4 = (const float4*)(g_V + (size_t)b * N_ * K_);
    for (int idx = t; idx < N_ * 4; idx += 256) {
        int j = idx >> 2, q = idx & 3;
        ((float4*)(Vs + j * 20))[q] = V4[idx];
    }
    __syncthreads();
    for (int j = t; j < N_; j += 256) {
        float q = 0.0f;
        #pragma unroll
        for (int k = 0; k < 16; ++k) { float v = Vs[j * 20 + k]; q += v * v; }
        qs[j] = q;
    }
    __syncthreads();

    // ---- Phase B: per-row reduction over j.
    float vi[16];
    #pragma unroll
    for (int q = 0; q < 4; ++q) {
        float4 v4 = ((const float4*)(Vs + i * 20))[q];
        vi[4*q] = v4.x; vi[4*q+1] = v4.y; vi[4*q+2] = v4.z; vi[4*q+3] = v4.w;
    }
    float qi = qs[i];

    float S0 = 0.0f, sac = 0.0f;
    float u[32];                          // u[0..15]=Sv, u[16..31]=Tv
    #pragma unroll
    for (int k = 0; k < 32; ++k) u[k] = 0.0f;

    const float* cbrow = cbs + w * N_;

    #pragma unroll 4
    for (int jj = 0; jj < 16; ++jj) {
        int j = lane + 32 * jj;
        float cb = cbrow[j];                 // lane-stride-1, conflict-free LDS

        float vj[16];
        #pragma unroll
        for (int q = 0; q < 4; ++q) {
            float4 uu = ((const float4*)(Vs + j * 20))[q];
            vj[4*q] = uu.x; vj[4*q+1] = uu.y; vj[4*q+2] = uu.z; vj[4*q+3] = uu.w;
        }
        float d0 = 0.0f, d1 = 0.0f;
        #pragma unroll
        for (int k = 0; k < 16; k += 2) { d0 += vi[k]*vj[k]; d1 += vi[k+1]*vj[k+1]; }
        float kl  = 0.5f * (qi + qs[j]) - (d0 + d1);   // / TAU = 1
        float wgt = cb * kl;
        S0  += cb;
        sac += wgt;
        #pragma unroll
        for (int k = 0; k < 16; ++k) {
            u[k]      += cb  * vj[k];
            u[16 + k] += wgt * vj[k];
        }
    }

    // ---- recursive-halving reduce-scatter of u[32]: 31 SHFL total.
    {
        bool hi = (lane & 16) != 0;
        #pragma unroll
        for (int k = 0; k < 16; ++k) {
            float send = hi ? u[k] : u[k + 16];
            float keep = hi ? u[k + 16] : u[k];
            u[k] = keep + __shfl_xor_sync(0xffffffffu, send, 16);
        }
        hi = (lane & 8) != 0;
        #pragma unroll
        for (int k = 0; k < 8; ++k) {
            float send = hi ? u[k] : u[k + 8];
            float keep = hi ? u[k + 8] : u[k];
            u[k] = keep + __shfl_xor_sync(0xffffffffu, send, 8);
        }
        hi = (lane & 4) != 0;
        #pragma unroll
        for (int k = 0; k < 4; ++k) {
            float send = hi ? u[k] : u[k + 4];
            float keep = hi ? u[k + 4] : u[k];
            u[k] = keep + __shfl_xor_sync(0xffffffffu, send, 4);
        }
        hi = (lane & 2) != 0;
        #pragma unroll
        for (int k = 0; k < 2; ++k) {
            float send = hi ? u[k] : u[k + 2];
            float keep = hi ? u[k + 2] : u[k];
            u[k] = keep + __shfl_xor_sync(0xffffffffu, send, 2);
        }
        hi = (lane & 1) != 0;
        {
            float send = hi ? u[0] : u[1];
            float keep = hi ? u[1] : u[0];
            u[0] = keep + __shfl_xor_sync(0xffffffffu, send, 1);
        }
    }
    // lane l (<16): u[0] = Sv[l]; lane l (>=16): u[0] = Tv[l-16]. Swap halves:
    float other = __shfl_xor_sync(0xffffffffu, u[0], 16);
    float Sv_f = (lane < 16) ? u[0] : other;
    float Tv_f = (lane < 16) ? other : u[0];

    // S0 / sac full butterfly (10 SHFL)
    #pragma unroll
    for (int off = 16; off > 0; off >>= 1) {
        S0  += __shfl_xor_sync(0xffffffffu, S0,  off);
        sac += __shfl_xor_sync(0xffffffffu, sac, off);
    }

    // rv component r, naturally distributed (lane r holds rv[r])
    float vik = vi[r];
    float rv_own = (S0 * vik - Sv_f)
                 + (sac * (1.0f - S0) * vik + sac * Sv_f - Tv_f);

    // Rotation grad = exp(A) rv
    float Ar[16];
    const float4* A4 = (const float4*)(g_A + (size_t)bn * 256 + r * 16);
    #pragma unroll
    for (int q = 0; q < 4; ++q) {
        float4 a = A4[q];
        Ar[4*q] = a.x; Ar[4*q+1] = a.y; Ar[4*q+2] = a.z; Ar[4*q+3] = a.w;
    }
    float grad = exp_apply<8>(Ar, rv_own);

    if (lane < 16) {
        float m  = mu[bn * 16 + lane];
        float mp = mu_prior[bn * 16 + lane];
        out[bn * 16 + lane] = m - lr * (0.001f * (m - mp) + grad);
    }
}

// ---------------------------------------------------------------------------
extern "C" void kernel_launch(void* const* d_in, const int* in_sizes, int n_in,
                              void* d_out, int out_size) {
    const float* mu       = (const float*)d_in[0];
    const float* beta     = (const float*)d_in[1];
    const float* mu_prior = (const float*)d_in[2];
    const float* phi      = (const float*)d_in[3];
    const float* gen      = (const float*)d_in[4];
    const float* lr       = (const float*)d_in[5];
    float* out = (float*)d_out;

    prep_kernel<<<BN / 8, 256>>>(mu, phi, gen);
    vffn_main_kernel<<<BN / 8, 256>>>(beta, mu, mu_prior, lr, out);
}

// round 17
// speedup vs baseline: 1.1116x; 1.1116x over previous
#include <cuda_runtime.h>
#include <cuda_bf16.h>

#define B_  8
#define H_  8
#define N_  512
#define K_  16
#define BN  (B_*N_)          // 4096
#define NN  (N_*N_)          // 262144

#define CHJ   64             // j-columns per chunk
#define NCH   (N_/CHJ)       // 8 chunks
#define STG   3              // smem ring stages
#define STGF  (H_*8*CHJ)     // floats per stage = 4096 (16 KB)

typedef unsigned int u32;

__device__ float g_A[BN * 256];     // per-(b,n) algebra element A, row-major 16x16
__device__ float g_V[BN * K_];      // v = exp(-A) mu

__device__ __forceinline__ void cp_async16(u32 dst_smem, const void* src) {
    asm volatile("cp.async.cg.shared.global [%0], [%1], 16;"
                 :: "r"(dst_smem), "l"(src) : "memory");
}
#define CP_COMMIT() asm volatile("cp.async.commit_group;" ::: "memory")
#define CP_WAIT(n)  asm volatile("cp.async.wait_group %0;" :: "n"(n) : "memory")

// ---------------------------------------------------------------------------
// Warp-collective: y = exp(A) x for a 16x16 A (M-term Taylor, Horner).
// Lane l owns row r = l&15 of A. x_own = component r of x (lanes 16-31 mirror).
// ---------------------------------------------------------------------------
template<int M>
__device__ __forceinline__ float exp_apply(const float Ar[16], float x_own) {
    float x[16], y[16];
    #pragma unroll
    for (int c = 0; c < 16; ++c) {
        x[c] = __shfl_sync(0xffffffffu, x_own, c);
        y[c] = x[c];
    }
    float y_own = x_own;
    #pragma unroll
    for (int k = M; k >= 1; --k) {
        float z0 = 0.0f, z1 = 0.0f;
        #pragma unroll
        for (int c = 0; c < 16; c += 2) {
            z0 += Ar[c]     * y[c];
            z1 += Ar[c + 1] * y[c + 1];
        }
        float zk = (z0 + z1) * (1.0f / (float)k);
        y_own = x_own + zk;
        #pragma unroll
        for (int c = 0; c < 16; ++c)
            y[c] = x[c] + __shfl_sync(0xffffffffu, zk, c);
    }
    return y_own;
}

// ---------------------------------------------------------------------------
// Kernel 0: per (b,n): A = sum_g phi_g G_g (store), v = exp(-A) mu (store).
// ---------------------------------------------------------------------------
__global__ __launch_bounds__(256)
void prep_kernel(const float* __restrict__ mu,
                 const float* __restrict__ phi,
                 const float* __restrict__ gen) {
    int w = threadIdx.x >> 5, lane = threadIdx.x & 31, r = lane & 15;
    int bn = blockIdx.x * 8 + w;

    float p0 = phi[bn * 3 + 0], p1 = phi[bn * 3 + 1], p2 = phi[bn * 3 + 2];

    float Ar[16];
    const float4* g4 = (const float4*)gen;
    #pragma unroll
    for (int q = 0; q < 4; ++q) {
        float4 a = g4[(0 * 256 + r * 16) / 4 + q];
        float4 b = g4[(1 * 256 + r * 16) / 4 + q];
        float4 c = g4[(2 * 256 + r * 16) / 4 + q];
        Ar[4 * q + 0] = p0 * a.x + p1 * b.x + p2 * c.x;
        Ar[4 * q + 1] = p0 * a.y + p1 * b.y + p2 * c.y;
        Ar[4 * q + 2] = p0 * a.z + p1 * b.z + p2 * c.z;
        Ar[4 * q + 3] = p0 * a.w + p1 * b.w + p2 * c.w;
    }
    if (lane < 16) {
        float4* A4 = (float4*)(g_A + (size_t)bn * 256 + r * 16);
        #pragma unroll
        for (int q = 0; q < 4; ++q)
            A4[q] = make_float4(Ar[4*q], Ar[4*q+1], Ar[4*q+2], Ar[4*q+3]);
    }

    float nAr[16];
    #pragma unroll
    for (int c = 0; c < 16; ++c) nAr[c] = -Ar[c];

    float x_own = mu[bn * 16 + r];
    float v = exp_apply<16>(nAr, x_own);
    if (lane < 16) g_V[bn * 16 + lane] = v;
}

// ---------------------------------------------------------------------------
// Kernel 1: cp.async-pipelined stream+compute. Block = 8 warps = 8 rows of
// one batch. Raw beta (8 heads x 8 rows) streams through a 3-stage smem ring
// in 64-column chunks via cp.async (no register residency -> 2 chunks always
// in flight per block). Consumers head-sum from smem and run the proven
// conflict-free reduction. DRAM stream genuinely overlaps compute.
// ---------------------------------------------------------------------------
__global__ __launch_bounds__(256)
void vffn_main_kernel(const float* __restrict__ beta,
                      const float* __restrict__ mu,
                      const float* __restrict__ mu_prior,
                      const float* __restrict__ lr_ptr,
                      float* __restrict__ out) {
    __shared__ float Vs[N_ * 20];        // 40 KB, stride-20 conflict-free
    __shared__ float qs[N_];             //  2 KB
    __shared__ float sbuf[STG * STGF];   // 48 KB ring: [stage][head][row][64j]

    int t = threadIdx.x, lane = t & 31, w = t >> 5, r = lane & 15;
    int b = blockIdx.x >> 6;                 // 64 blocks per batch
    int i0 = (blockIdx.x & 63) << 3;
    int i = i0 + w;                          // this warp's row
    int bn = b * N_ + i;
    float lr = *lr_ptr;

    // cp.async thread mapping: h = t>>5, row = 2k + ((t>>4)&1), g = t&15 (16B)
    int ch   = t >> 5;
    int half = (t >> 4) & 1;
    int cg   = t & 15;
    const float* csrc = beta + (size_t)b * H_ * NN + (size_t)ch * NN
                      + (size_t)i0 * N_ + cg * 4;
    u32 sbase = (u32)__cvta_generic_to_shared(sbuf);
    u32 cdst  = sbase + ((u32)(ch * 8) * CHJ + cg * 4) * 4;

    // Issue chunks 0 and 1 immediately (DRAM starts before anything else)
    #pragma unroll
    for (int cc = 0; cc < 2; ++cc) {
        #pragma unroll
        for (int k = 0; k < 4; ++k) {
            int row = 2 * k + half;
            cp_async16(cdst + (u32)(cc * STGF + row * CHJ) * 4,
                       csrc + (size_t)row * N_ + cc * CHJ);
        }
        CP_COMMIT();
    }

    // Stage V[b] into padded smem (stride 20 floats; float4-aligned)
    const float4* V4 = (const float4*)(g_V + (size_t)b * N_ * K_);
    for (int idx = t; idx < N_ * 4; idx += 256) {
        int j = idx >> 2, q = idx & 3;
        ((float4*)(Vs + j * 20))[q] = V4[idx];
    }
    __syncthreads();
    for (int j = t; j < N_; j += 256) {
        float q = 0.0f;
        #pragma unroll
        for (int k = 0; k < 16; ++k) { float v = Vs[j * 20 + k]; q += v * v; }
        qs[j] = q;
    }
    __syncthreads();

    float vi[16];
    #pragma unroll
    for (int q = 0; q < 4; ++q) {
        float4 v4 = ((const float4*)(Vs + i * 20))[q];
        vi[4*q] = v4.x; vi[4*q+1] = v4.y; vi[4*q+2] = v4.z; vi[4*q+3] = v4.w;
    }
    float qi = qs[i];

    float S0 = 0.0f, sac = 0.0f;
    float u[32];                          // u[0..15]=Sv, u[16..31]=Tv
    #pragma unroll
    for (int k = 0; k < 32; ++k) u[k] = 0.0f;

    #pragma unroll 1
    for (int c = 0; c < NCH; ++c) {
        if (c == NCH - 1) { CP_WAIT(0); } else { CP_WAIT(1); }
        __syncthreads();

        int s = c % STG;
        const float* sb = sbuf + s * STGF;

        #pragma unroll
        for (int q = 0; q < 2; ++q) {
            int jl = lane + 32 * q;
            int j  = CHJ * c + jl;

            // head-average from raw smem (lane-stride-1, conflict-free)
            float cs0 = sb[(0*8 + w)*CHJ + jl] + sb[(1*8 + w)*CHJ + jl];
            float cs1 = sb[(2*8 + w)*CHJ + jl] + sb[(3*8 + w)*CHJ + jl];
            float cs2 = sb[(4*8 + w)*CHJ + jl] + sb[(5*8 + w)*CHJ + jl];
            float cs3 = sb[(6*8 + w)*CHJ + jl] + sb[(7*8 + w)*CHJ + jl];
            float cb  = ((cs0 + cs1) + (cs2 + cs3)) * 0.125f;

            float vj[16];
            #pragma unroll
            for (int p = 0; p < 4; ++p) {
                float4 uu = ((const float4*)(Vs + j * 20))[p];
                vj[4*p] = uu.x; vj[4*p+1] = uu.y; vj[4*p+2] = uu.z; vj[4*p+3] = uu.w;
            }
            float d0 = 0.0f, d1 = 0.0f;
            #pragma unroll
            for (int k = 0; k < 16; k += 2) { d0 += vi[k]*vj[k]; d1 += vi[k+1]*vj[k+1]; }
            float kl  = 0.5f * (qi + qs[j]) - (d0 + d1);   // / TAU = 1
            float wgt = cb * kl;
            S0  += cb;
            sac += wgt;
            #pragma unroll
            for (int k = 0; k < 16; ++k) {
                u[k]      += cb  * vj[k];
                u[16 + k] += wgt * vj[k];
            }
        }

        __syncthreads();
        if (c + 2 < NCH) {
            int cc = c + 2;
            int s2 = cc % STG;
            #pragma unroll
            for (int k = 0; k < 4; ++k) {
                int row = 2 * k + half;
                cp_async16(cdst + (u32)(s2 * STGF + row * CHJ) * 4,
                           csrc + (size_t)row * N_ + cc * CHJ);
            }
            CP_COMMIT();
        }
    }

    // ---- recursive-halving reduce-scatter of u[32]: 31 SHFL total.
    {
        bool hi = (lane & 16) != 0;
        #pragma unroll
        for (int k = 0; k < 16; ++k) {
            float send = hi ? u[k] : u[k + 16];
            float keep = hi ? u[k + 16] : u[k];
            u[k] = keep + __shfl_xor_sync(0xffffffffu, send, 16);
        }
        hi = (lane & 8) != 0;
        #pragma unroll
        for (int k = 0; k < 8; ++k) {
            float send = hi ? u[k] : u[k + 8];
            float keep = hi ? u[k + 8] : u[k];
            u[k] = keep + __shfl_xor_sync(0xffffffffu, send, 8);
        }
        hi = (lane & 4) != 0;
        #pragma unroll
        for (int k = 0; k < 4; ++k) {
            float send = hi ? u[k] : u[k + 4];
            float keep = hi ? u[k + 4] : u[k];
            u[k] = keep + __shfl_xor_sync(0xffffffffu, send, 4);
        }
        hi = (lane & 2) != 0;
        #pragma unroll
        for (int k = 0; k < 2; ++k) {
            float send = hi ? u[k] : u[k + 2];
            float keep = hi ? u[k + 2] : u[k];
            u[k] = keep + __shfl_xor_sync(0xffffffffu, send, 2);
        }
        hi = (lane & 1) != 0;
        {
            float send = hi ? u[0] : u[1];
            float keep = hi ? u[1] : u[0];
            u[0] = keep + __shfl_xor_sync(0xffffffffu, send, 1);
        }
    }
    float other = __shfl_xor_sync(0xffffffffu, u[0], 16);
    float Sv_f = (lane < 16) ? u[0] : other;
    float Tv_f = (lane < 16) ? other : u[0];

    #pragma unroll
    for (int off = 16; off > 0; off >>= 1) {
        S0  += __shfl_xor_sync(0xffffffffu, S0,  off);
        sac += __shfl_xor_sync(0xffffffffu, sac, off);
    }

    // rv component r, naturally distributed (lane r holds rv[r])
    float vik = vi[r];
    float rv_own = (S0 * vik - Sv_f)
                 + (sac * (1.0f - S0) * vik + sac * Sv_f - Tv_f);

    // Rotation grad = exp(A) rv
    float Ar[16];
    const float4* A4 = (const float4*)(g_A + (size_t)bn * 256 + r * 16);
    #pragma unroll
    for (int q = 0; q < 4; ++q) {
        float4 a = A4[q];
        Ar[4*q] = a.x; Ar[4*q+1] = a.y; Ar[4*q+2] = a.z; Ar[4*q+3] = a.w;
    }
    float grad = exp_apply<8>(Ar, rv_own);

    if (lane < 16) {
        float m  = mu[bn * 16 + lane];
        float mp = mu_prior[bn * 16 + lane];
        out[bn * 16 + lane] = m - lr * (0.001f * (m - mp) + grad);
    }
}

// ---------------------------------------------------------------------------
extern "C" void kernel_launch(void* const* d_in, const int* in_sizes, int n_in,
                              void* d_out, int out_size) {
    const float* mu       = (const float*)d_in[0];
    const float* beta     = (const float*)d_in[1];
    const float* mu_prior = (const float*)d_in[2];
    const float* phi      = (const float*)d_in[3];
    const float* gen      = (const float*)d_in[4];
    const float* lr       = (const float*)d_in[5];
    float* out = (float*)d_out;

    prep_kernel<<<BN / 8, 256>>>(mu, phi, gen);
    vffn_main_kernel<<<BN / 8, 256>>>(beta, mu, mu_prior, lr, out);
}